// round 1
// baseline (speedup 1.0000x reference)
#include <cuda_runtime.h>
#include <cstdint>
#include <math.h>

// Causal attention: B=2, H=16, S=2048, D=64, fp32 in/out.
// Flash-attention, TF32 mma.sync (m16n8k8), fp32 accumulate.
// Inputs: d_in[0]=V, d_in[1]=Q, d_in[2]=K, d_in[3]=Fk(unused, =64), d_in[4]=mask(unused, causal).

#define SEQ 2048
#define HD  64
#define BR  64
#define BC  64
#define NW  4
#define STRIDE 68   // padded smem row stride (floats) -> conflict-free frag loads

__device__ __forceinline__ uint32_t f2tf32(float f) {
    uint32_t u;
    asm("cvt.rna.tf32.f32 %0, %1;" : "=r"(u) : "f"(f));
    return u;
}

__device__ __forceinline__ void mma_tf32(float* c, const uint32_t* a, uint32_t b0, uint32_t b1) {
    asm volatile(
        "mma.sync.aligned.m16n8k8.row.col.f32.tf32.tf32.f32 "
        "{%0,%1,%2,%3}, {%4,%5,%6,%7}, {%8,%9}, {%0,%1,%2,%3};\n"
        : "+f"(c[0]), "+f"(c[1]), "+f"(c[2]), "+f"(c[3])
        : "r"(a[0]), "r"(a[1]), "r"(a[2]), "r"(a[3]), "r"(b0), "r"(b1));
}

__global__ __launch_bounds__(128) void fa_tf32_kernel(
    const float* __restrict__ Q,
    const float* __restrict__ K,
    const float* __restrict__ V,
    float* __restrict__ O)
{
    // sK doubles as the P buffer after the S-gemm is done with it.
    __shared__ uint32_t sK[BC * STRIDE];
    __shared__ uint32_t sV[BC * STRIDE];

    const int tid  = threadIdx.x;
    const int lane = tid & 31;
    const int warp = tid >> 5;
    const int g    = lane >> 2;   // group id (row within fragment)
    const int t    = lane & 3;    // thread in group

    const int qtile = (int)gridDim.x - 1 - (int)blockIdx.x;  // heavy tiles first
    const int bh    = blockIdx.y;
    const int q0    = qtile * BR;

    const float scale = 0.125f;  // 1/sqrt(64)

    // ---- Load Q fragments (row-major A frags for m16n8k8), scale folded in ----
    const float* Qb = Q + ((size_t)bh * SEQ + q0 + warp * 16) * HD;
    uint32_t qa[8][4];
#pragma unroll
    for (int kt = 0; kt < 8; kt++) {
        qa[kt][0] = f2tf32(Qb[(g)     * HD + kt * 8 + t]     * scale);
        qa[kt][1] = f2tf32(Qb[(g + 8) * HD + kt * 8 + t]     * scale);
        qa[kt][2] = f2tf32(Qb[(g)     * HD + kt * 8 + t + 4] * scale);
        qa[kt][3] = f2tf32(Qb[(g + 8) * HD + kt * 8 + t + 4] * scale);
    }

    float oacc[8][4];
#pragma unroll
    for (int n = 0; n < 8; n++)
#pragma unroll
        for (int i = 0; i < 4; i++) oacc[n][i] = 0.0f;

    float m0 = -INFINITY, m1 = -INFINITY;  // running row max (rows g, g+8)
    float l0 = 0.0f, l1 = 0.0f;            // running row sum

    const int row0 = q0 + warp * 16 + g;
    const int row1 = row0 + 8;

    for (int j = 0; j <= qtile; j++) {
        __syncthreads();  // protect sK(P)/sV from previous iteration's readers

        // ---- Load K,V tile j into smem as TF32 (float4 gmem reads) ----
        const float* Kt = K + ((size_t)bh * SEQ + j * BC) * HD;
        const float* Vt = V + ((size_t)bh * SEQ + j * BC) * HD;
#pragma unroll
        for (int i = 0; i < 8; i++) {
            int idx = tid + i * 128;
            int r = idx >> 4;           // 16 float4 per 64-float row
            int c = (idx & 15) * 4;
            float4 k4 = *(const float4*)(Kt + r * HD + c);
            float4 v4 = *(const float4*)(Vt + r * HD + c);
            uint4 ku, vu;
            ku.x = f2tf32(k4.x); ku.y = f2tf32(k4.y); ku.z = f2tf32(k4.z); ku.w = f2tf32(k4.w);
            vu.x = f2tf32(v4.x); vu.y = f2tf32(v4.y); vu.z = f2tf32(v4.z); vu.w = f2tf32(v4.w);
            *(uint4*)&sK[r * STRIDE + c] = ku;
            *(uint4*)&sV[r * STRIDE + c] = vu;
        }
        __syncthreads();

        // ---- S = Q @ K^T ----
        float sacc[8][4];
#pragma unroll
        for (int n = 0; n < 8; n++)
#pragma unroll
            for (int i = 0; i < 4; i++) sacc[n][i] = 0.0f;

#pragma unroll
        for (int n = 0; n < 8; n++) {
#pragma unroll
            for (int kt = 0; kt < 8; kt++) {
                // B[k][nn] = K[col][k]; col = n*8+g; banks conflict-free w/ stride 68
                uint32_t b0 = sK[(n * 8 + g) * STRIDE + kt * 8 + t];
                uint32_t b1 = sK[(n * 8 + g) * STRIDE + kt * 8 + t + 4];
                mma_tf32(sacc[n], qa[kt], b0, b1);
            }
        }

        // ---- causal mask on diagonal tile ----
        if (j == qtile) {
#pragma unroll
            for (int n = 0; n < 8; n++) {
                int col = j * BC + n * 8 + 2 * t;
                if (col     > row0) sacc[n][0] = -1e30f;
                if (col + 1 > row0) sacc[n][1] = -1e30f;
                if (col     > row1) sacc[n][2] = -1e30f;
                if (col + 1 > row1) sacc[n][3] = -1e30f;
            }
        }

        // ---- online softmax ----
        float tm0 = -INFINITY, tm1 = -INFINITY;
#pragma unroll
        for (int n = 0; n < 8; n++) {
            tm0 = fmaxf(tm0, fmaxf(sacc[n][0], sacc[n][1]));
            tm1 = fmaxf(tm1, fmaxf(sacc[n][2], sacc[n][3]));
        }
        tm0 = fmaxf(tm0, __shfl_xor_sync(0xFFFFFFFFu, tm0, 1));
        tm0 = fmaxf(tm0, __shfl_xor_sync(0xFFFFFFFFu, tm0, 2));
        tm1 = fmaxf(tm1, __shfl_xor_sync(0xFFFFFFFFu, tm1, 1));
        tm1 = fmaxf(tm1, __shfl_xor_sync(0xFFFFFFFFu, tm1, 2));

        float mn0 = fmaxf(m0, tm0);
        float mn1 = fmaxf(m1, tm1);
        float a0 = __expf(m0 - mn0);
        float a1 = __expf(m1 - mn1);

        float ls0 = 0.0f, ls1 = 0.0f;
#pragma unroll
        for (int n = 0; n < 8; n++) {
            sacc[n][0] = __expf(sacc[n][0] - mn0);
            sacc[n][1] = __expf(sacc[n][1] - mn0);
            sacc[n][2] = __expf(sacc[n][2] - mn1);
            sacc[n][3] = __expf(sacc[n][3] - mn1);
            ls0 += sacc[n][0] + sacc[n][1];
            ls1 += sacc[n][2] + sacc[n][3];
        }
        ls0 += __shfl_xor_sync(0xFFFFFFFFu, ls0, 1);
        ls0 += __shfl_xor_sync(0xFFFFFFFFu, ls0, 2);
        ls1 += __shfl_xor_sync(0xFFFFFFFFu, ls1, 1);
        ls1 += __shfl_xor_sync(0xFFFFFFFFu, ls1, 2);

        l0 = l0 * a0 + ls0;
        l1 = l1 * a1 + ls1;
        m0 = mn0;
        m1 = mn1;

#pragma unroll
        for (int n = 0; n < 8; n++) {
            oacc[n][0] *= a0; oacc[n][1] *= a0;
            oacc[n][2] *= a1; oacc[n][3] *= a1;
        }

        __syncthreads();  // everyone done reading sK before we overwrite it with P

        // ---- write P (TF32) into sK region; each warp owns its 16 rows ----
        uint32_t* sP = sK;
        const int pr0 = warp * 16 + g;
#pragma unroll
        for (int n = 0; n < 8; n++) {
            sP[(pr0)     * STRIDE + n * 8 + 2 * t]     = f2tf32(sacc[n][0]);
            sP[(pr0)     * STRIDE + n * 8 + 2 * t + 1] = f2tf32(sacc[n][1]);
            sP[(pr0 + 8) * STRIDE + n * 8 + 2 * t]     = f2tf32(sacc[n][2]);
            sP[(pr0 + 8) * STRIDE + n * 8 + 2 * t + 1] = f2tf32(sacc[n][3]);
        }
        __syncwarp();  // each warp only reads back its own P slice

        // ---- O += P @ V ----
#pragma unroll
        for (int kt = 0; kt < 8; kt++) {
            uint32_t pa[4];
            pa[0] = sP[(pr0)     * STRIDE + kt * 8 + t];
            pa[1] = sP[(pr0 + 8) * STRIDE + kt * 8 + t];
            pa[2] = sP[(pr0)     * STRIDE + kt * 8 + t + 4];
            pa[3] = sP[(pr0 + 8) * STRIDE + kt * 8 + t + 4];
#pragma unroll
            for (int dn = 0; dn < 8; dn++) {
                uint32_t b0 = sV[(kt * 8 + t)     * STRIDE + dn * 8 + g];
                uint32_t b1 = sV[(kt * 8 + t + 4) * STRIDE + dn * 8 + g];
                mma_tf32(oacc[dn], pa, b0, b1);
            }
        }
    }

    // ---- epilogue: normalize and store ----
    const float inv0 = 1.0f / l0;
    const float inv1 = 1.0f / l1;
    float* Ob = O + ((size_t)bh * SEQ + q0 + warp * 16) * HD;
#pragma unroll
    for (int dn = 0; dn < 8; dn++) {
        float2 v0 = make_float2(oacc[dn][0] * inv0, oacc[dn][1] * inv0);
        float2 v1 = make_float2(oacc[dn][2] * inv1, oacc[dn][3] * inv1);
        *(float2*)(Ob + (g)     * HD + dn * 8 + 2 * t) = v0;
        *(float2*)(Ob + (g + 8) * HD + dn * 8 + 2 * t) = v1;
    }
}

extern "C" void kernel_launch(void* const* d_in, const int* in_sizes, int n_in,
                              void* d_out, int out_size) {
    const float* V = (const float*)d_in[0];
    const float* Q = (const float*)d_in[1];
    const float* K = (const float*)d_in[2];
    float* O = (float*)d_out;

    dim3 grid(SEQ / BR, 32);  // (32 q-tiles, B*H heads)
    dim3 block(128);
    fa_tf32_kernel<<<grid, block>>>(Q, K, V, O);
}

// round 2
// speedup vs baseline: 1.2469x; 1.2469x over previous
#include <cuda_runtime.h>
#include <cstdint>
#include <math.h>

// Causal attention: B=2, H=16, S=2048, D=64, fp32 in/out.
// Flash-attention, TF32 mma.sync (m16n8k8), fp32 accumulate.
// Round 2: sigma-permuted S-gemm columns (P stays in registers, no smem
// round-trip), sV stride 72 (conflict-free V-gemm loads), launch_bounds(128,4).
// Inputs: d_in[0]=V, d_in[1]=Q, d_in[2]=K, d_in[3]=Fk(=64), d_in[4]=mask(causal).

#define SEQ 2048
#define HD  64
#define BR  64
#define BC  64
#define KSTR 68   // sK row stride (floats): conflict-free for S-gemm B loads
#define VSTR 72   // sV row stride (floats): conflict-free for V-gemm B loads

__device__ __forceinline__ uint32_t f2tf32(float f) {
    uint32_t u;
    asm("cvt.rna.tf32.f32 %0, %1;" : "=r"(u) : "f"(f));
    return u;
}

__device__ __forceinline__ void mma_tf32(float* c, const uint32_t* a, uint32_t b0, uint32_t b1) {
    asm volatile(
        "mma.sync.aligned.m16n8k8.row.col.f32.tf32.tf32.f32 "
        "{%0,%1,%2,%3}, {%4,%5,%6,%7}, {%8,%9}, {%0,%1,%2,%3};\n"
        : "+f"(c[0]), "+f"(c[1]), "+f"(c[2]), "+f"(c[3])
        : "r"(a[0]), "r"(a[1]), "r"(a[2]), "r"(a[3]), "r"(b0), "r"(b1));
}

__global__ __launch_bounds__(128, 4) void fa_tf32_kernel(
    const float* __restrict__ Q,
    const float* __restrict__ K,
    const float* __restrict__ V,
    float* __restrict__ O)
{
    __shared__ uint32_t sK[BC * KSTR];
    __shared__ uint32_t sV[BC * VSTR];

    const int tid  = threadIdx.x;
    const int lane = tid & 31;
    const int warp = tid >> 5;
    const int g    = lane >> 2;   // group id (row within fragment)
    const int t    = lane & 3;    // thread in group

    // sigma(g): which K row feeds mma column nn=g.  sigma = [0,4,1,5,2,6,3,7]
    // => C-frag element c0 (col 2t) holds score vs K row t; c1 (col 2t+1) vs row t+4.
    const int sg = (g & 1) ? ((g >> 1) + 4) : (g >> 1);

    const int qtile = (int)gridDim.x - 1 - (int)blockIdx.x;  // heavy tiles first
    const int bh    = blockIdx.y;
    const int q0    = qtile * BR;

    const float scale = 0.125f;  // 1/sqrt(64)

    // ---- Load Q fragments (row-major A frags for m16n8k8), scale folded in ----
    const float* Qb = Q + ((size_t)bh * SEQ + q0 + warp * 16) * HD;
    uint32_t qa[8][4];
#pragma unroll
    for (int kt = 0; kt < 8; kt++) {
        qa[kt][0] = f2tf32(Qb[(g)     * HD + kt * 8 + t]     * scale);
        qa[kt][1] = f2tf32(Qb[(g + 8) * HD + kt * 8 + t]     * scale);
        qa[kt][2] = f2tf32(Qb[(g)     * HD + kt * 8 + t + 4] * scale);
        qa[kt][3] = f2tf32(Qb[(g + 8) * HD + kt * 8 + t + 4] * scale);
    }

    float oacc[8][4];
#pragma unroll
    for (int n = 0; n < 8; n++)
#pragma unroll
        for (int i = 0; i < 4; i++) oacc[n][i] = 0.0f;

    float m0 = -INFINITY, m1 = -INFINITY;  // running row max (rows g, g+8)
    float l0 = 0.0f, l1 = 0.0f;            // running row sum

    const int row0 = q0 + warp * 16 + g;
    const int row1 = row0 + 8;

    for (int j = 0; j <= qtile; j++) {
        __syncthreads();  // all warps done reading previous sK/sV

        // ---- Load K,V tile j into smem as TF32 (float4 gmem reads) ----
        const float* Kt = K + ((size_t)bh * SEQ + j * BC) * HD;
        const float* Vt = V + ((size_t)bh * SEQ + j * BC) * HD;
#pragma unroll
        for (int i = 0; i < 8; i++) {
            int idx = tid + i * 128;
            int r = idx >> 4;           // 16 float4 per 64-float row
            int c = (idx & 15) * 4;
            float4 k4 = *(const float4*)(Kt + r * HD + c);
            float4 v4 = *(const float4*)(Vt + r * HD + c);
            uint4 ku, vu;
            ku.x = f2tf32(k4.x); ku.y = f2tf32(k4.y); ku.z = f2tf32(k4.z); ku.w = f2tf32(k4.w);
            vu.x = f2tf32(v4.x); vu.y = f2tf32(v4.y); vu.z = f2tf32(v4.z); vu.w = f2tf32(v4.w);
            *(uint4*)&sK[r * KSTR + c] = ku;
            *(uint4*)&sV[r * VSTR + c] = vu;
        }
        __syncthreads();

        // ---- S = Q @ K^T  (columns sigma-permuted) ----
        float sacc[8][4];
#pragma unroll
        for (int n = 0; n < 8; n++)
#pragma unroll
            for (int i = 0; i < 4; i++) sacc[n][i] = 0.0f;

        const uint32_t* sKb = sK + sg * KSTR + t;  // B col nn=g reads K row n*8+sg
#pragma unroll
        for (int n = 0; n < 8; n++) {
#pragma unroll
            for (int kt = 0; kt < 8; kt++) {
                uint32_t b0 = sKb[n * 8 * KSTR + kt * 8];
                uint32_t b1 = sKb[n * 8 * KSTR + kt * 8 + 4];
                mma_tf32(sacc[n], qa[kt], b0, b1);
            }
        }

        // ---- causal mask on diagonal tile (sigma-adjusted columns) ----
        if (j == qtile) {
#pragma unroll
            for (int n = 0; n < 8; n++) {
                int col = j * BC + n * 8 + t;   // c0/c2 column; c1/c3 is col+4
                if (col     > row0) sacc[n][0] = -1e30f;
                if (col + 4 > row0) sacc[n][1] = -1e30f;
                if (col     > row1) sacc[n][2] = -1e30f;
                if (col + 4 > row1) sacc[n][3] = -1e30f;
            }
        }

        // ---- online softmax ----
        float tm0 = -INFINITY, tm1 = -INFINITY;
#pragma unroll
        for (int n = 0; n < 8; n++) {
            tm0 = fmaxf(tm0, fmaxf(sacc[n][0], sacc[n][1]));
            tm1 = fmaxf(tm1, fmaxf(sacc[n][2], sacc[n][3]));
        }
        tm0 = fmaxf(tm0, __shfl_xor_sync(0xFFFFFFFFu, tm0, 1));
        tm0 = fmaxf(tm0, __shfl_xor_sync(0xFFFFFFFFu, tm0, 2));
        tm1 = fmaxf(tm1, __shfl_xor_sync(0xFFFFFFFFu, tm1, 1));
        tm1 = fmaxf(tm1, __shfl_xor_sync(0xFFFFFFFFu, tm1, 2));

        float mn0 = fmaxf(m0, tm0);
        float mn1 = fmaxf(m1, tm1);
        float a0 = __expf(m0 - mn0);
        float a1 = __expf(m1 - mn1);

        float ls0 = 0.0f, ls1 = 0.0f;
#pragma unroll
        for (int n = 0; n < 8; n++) {
            sacc[n][0] = __expf(sacc[n][0] - mn0);
            sacc[n][1] = __expf(sacc[n][1] - mn0);
            sacc[n][2] = __expf(sacc[n][2] - mn1);
            sacc[n][3] = __expf(sacc[n][3] - mn1);
            ls0 += sacc[n][0] + sacc[n][1];
            ls1 += sacc[n][2] + sacc[n][3];
        }
        ls0 += __shfl_xor_sync(0xFFFFFFFFu, ls0, 1);
        ls0 += __shfl_xor_sync(0xFFFFFFFFu, ls0, 2);
        ls1 += __shfl_xor_sync(0xFFFFFFFFu, ls1, 1);
        ls1 += __shfl_xor_sync(0xFFFFFFFFu, ls1, 2);

        l0 = l0 * a0 + ls0;
        l1 = l1 * a1 + ls1;
        m0 = mn0;
        m1 = mn1;

#pragma unroll
        for (int n = 0; n < 8; n++) {
            oacc[n][0] *= a0; oacc[n][1] *= a0;
            oacc[n][2] *= a1; oacc[n][3] *= a1;
        }

        // ---- O += P @ V : sacc IS the A-fragment (thanks to sigma) ----
        const uint32_t* sVb = sV + t * VSTR + g;  // B[k=kt*8+t][n=dn*8+g]
#pragma unroll
        for (int kt = 0; kt < 8; kt++) {
            uint32_t pa[4];
            pa[0] = f2tf32(sacc[kt][0]);  // P[row g   ][kt*8 + t    ]
            pa[1] = f2tf32(sacc[kt][2]);  // P[row g+8 ][kt*8 + t    ]
            pa[2] = f2tf32(sacc[kt][1]);  // P[row g   ][kt*8 + t + 4]
            pa[3] = f2tf32(sacc[kt][3]);  // P[row g+8 ][kt*8 + t + 4]
#pragma unroll
            for (int dn = 0; dn < 8; dn++) {
                uint32_t b0 = sVb[(kt * 8)     * VSTR + dn * 8];
                uint32_t b1 = sVb[(kt * 8 + 4) * VSTR + dn * 8];
                mma_tf32(oacc[dn], pa, b0, b1);
            }
        }
    }

    // ---- epilogue: normalize and store ----
    const float inv0 = 1.0f / l0;
    const float inv1 = 1.0f / l1;
    float* Ob = O + ((size_t)bh * SEQ + q0 + warp * 16) * HD;
#pragma unroll
    for (int dn = 0; dn < 8; dn++) {
        float2 v0 = make_float2(oacc[dn][0] * inv0, oacc[dn][1] * inv0);
        float2 v1 = make_float2(oacc[dn][2] * inv1, oacc[dn][3] * inv1);
        *(float2*)(Ob + (g)     * HD + dn * 8 + 2 * t) = v0;
        *(float2*)(Ob + (g + 8) * HD + dn * 8 + 2 * t) = v1;
    }
}

extern "C" void kernel_launch(void* const* d_in, const int* in_sizes, int n_in,
                              void* d_out, int out_size) {
    const float* V = (const float*)d_in[0];
    const float* Q = (const float*)d_in[1];
    const float* K = (const float*)d_in[2];
    float* O = (float*)d_out;

    dim3 grid(SEQ / BR, 32);  // (32 q-tiles, B*H heads)
    dim3 block(128);
    fa_tf32_kernel<<<grid, block>>>(Q, K, V, O);
}

// round 3
// speedup vs baseline: 1.2598x; 1.0103x over previous
#include <cuda_runtime.h>
#include <cstdint>
#include <math.h>

// Causal attention: B=2, H=16, S=2048, D=64, fp32 in/out.
// Flash-attention, TF32 mma.sync (m16n8k8), fp32 accumulate.
// Round 3: M=32 per warp (two 16-row strips) -> each B-fragment LDS pair feeds
// TWO mmas, halving the binding L1/LDS traffic per tensor op. BR=128 per CTA.
// Inputs: d_in[0]=V, d_in[1]=Q, d_in[2]=K, d_in[3]=Fk(=64), d_in[4]=mask(causal).

#define SEQ 2048
#define HD  64
#define BR  128   // Q rows per CTA (4 warps x 32 rows)
#define BC  64    // KV rows per tile
#define KSTR 68   // sK row stride (floats): conflict-free for S-gemm B loads
#define VSTR 72   // sV row stride (floats): conflict-free for V-gemm B loads

__device__ __forceinline__ uint32_t f2tf32(float f) {
    uint32_t u;
    asm("cvt.rna.tf32.f32 %0, %1;" : "=r"(u) : "f"(f));
    return u;
}

__device__ __forceinline__ void mma_tf32(float* c, const uint32_t* a, uint32_t b0, uint32_t b1) {
    asm volatile(
        "mma.sync.aligned.m16n8k8.row.col.f32.tf32.tf32.f32 "
        "{%0,%1,%2,%3}, {%4,%5,%6,%7}, {%8,%9}, {%0,%1,%2,%3};\n"
        : "+f"(c[0]), "+f"(c[1]), "+f"(c[2]), "+f"(c[3])
        : "r"(a[0]), "r"(a[1]), "r"(a[2]), "r"(a[3]), "r"(b0), "r"(b1));
}

__global__ __launch_bounds__(128, 2) void fa_tf32_kernel(
    const float* __restrict__ Q,
    const float* __restrict__ K,
    const float* __restrict__ V,
    float* __restrict__ O)
{
    __shared__ uint32_t sK[BC * KSTR];
    __shared__ uint32_t sV[BC * VSTR];

    const int tid  = threadIdx.x;
    const int lane = tid & 31;
    const int warp = tid >> 5;
    const int g    = lane >> 2;   // group id (row within fragment)
    const int t    = lane & 3;    // thread in group

    // sigma(g): which K row feeds mma column nn=g.  sigma = [0,4,1,5,2,6,3,7]
    // => C-frag c0 (col 2t) holds score vs K row t; c1 (col 2t+1) vs row t+4,
    // so sacc doubles directly as the A-fragment of the P@V gemm.
    const int sg = (g & 1) ? ((g >> 1) + 4) : (g >> 1);

    const int qtile = (int)gridDim.x - 1 - (int)blockIdx.x;  // heavy tiles first
    const int bh    = blockIdx.y;
    const int q0    = qtile * BR;
    const int wbase = q0 + warp * 32;     // first Q row of this warp

    const float scale = 0.125f;  // 1/sqrt(64)

    // ---- Load Q fragments for both strips, scale folded in ----
    const float* Qb = Q + ((size_t)bh * SEQ + wbase) * HD;
    uint32_t qa[2][8][4];
#pragma unroll
    for (int s = 0; s < 2; s++) {
#pragma unroll
        for (int kt = 0; kt < 8; kt++) {
            qa[s][kt][0] = f2tf32(Qb[(s * 16 + g)     * HD + kt * 8 + t]     * scale);
            qa[s][kt][1] = f2tf32(Qb[(s * 16 + g + 8) * HD + kt * 8 + t]     * scale);
            qa[s][kt][2] = f2tf32(Qb[(s * 16 + g)     * HD + kt * 8 + t + 4] * scale);
            qa[s][kt][3] = f2tf32(Qb[(s * 16 + g + 8) * HD + kt * 8 + t + 4] * scale);
        }
    }

    float oacc[2][8][4];
#pragma unroll
    for (int s = 0; s < 2; s++)
#pragma unroll
        for (int n = 0; n < 8; n++)
#pragma unroll
            for (int i = 0; i < 4; i++) oacc[s][n][i] = 0.0f;

    float mrow[2][2] = {{-INFINITY, -INFINITY}, {-INFINITY, -INFINITY}};
    float lrow[2][2] = {{0.0f, 0.0f}, {0.0f, 0.0f}};

    const int jmax = (q0 + BR - 1) / BC;   // last KV tile index (= 2*qtile+1)

    for (int j = 0; j <= jmax; j++) {
        __syncthreads();  // all warps done reading previous sK/sV

        // ---- Load K,V tile j into smem as TF32 (float4 gmem reads) ----
        const float* Kt = K + ((size_t)bh * SEQ + j * BC) * HD;
        const float* Vt = V + ((size_t)bh * SEQ + j * BC) * HD;
#pragma unroll
        for (int i = 0; i < 8; i++) {
            int idx = tid + i * 128;
            int r = idx >> 4;           // 16 float4 per 64-float row
            int c = (idx & 15) * 4;
            float4 k4 = *(const float4*)(Kt + r * HD + c);
            float4 v4 = *(const float4*)(Vt + r * HD + c);
            uint4 ku, vu;
            ku.x = f2tf32(k4.x); ku.y = f2tf32(k4.y); ku.z = f2tf32(k4.z); ku.w = f2tf32(k4.w);
            vu.x = f2tf32(v4.x); vu.y = f2tf32(v4.y); vu.z = f2tf32(v4.z); vu.w = f2tf32(v4.w);
            *(uint4*)&sK[r * KSTR + c] = ku;
            *(uint4*)&sV[r * VSTR + c] = vu;
        }
        __syncthreads();

        // ---- S = Q @ K^T  (columns sigma-permuted); one B-load -> two mmas ----
        float sacc[2][8][4];
#pragma unroll
        for (int s = 0; s < 2; s++)
#pragma unroll
            for (int n = 0; n < 8; n++)
#pragma unroll
                for (int i = 0; i < 4; i++) sacc[s][n][i] = 0.0f;

        const uint32_t* sKb = sK + sg * KSTR + t;
#pragma unroll
        for (int n = 0; n < 8; n++) {
#pragma unroll
            for (int kt = 0; kt < 8; kt++) {
                uint32_t b0 = sKb[n * 8 * KSTR + kt * 8];
                uint32_t b1 = sKb[n * 8 * KSTR + kt * 8 + 4];
                mma_tf32(sacc[0][n], qa[0][kt], b0, b1);
                mma_tf32(sacc[1][n], qa[1][kt], b0, b1);
            }
        }

        // ---- causal mask (per strip; only near-diagonal tiles) ----
#pragma unroll
        for (int s = 0; s < 2; s++) {
            if (j * BC + (BC - 1) > wbase + s * 16) {
                int row0 = wbase + s * 16 + g;
                int row1 = row0 + 8;
#pragma unroll
                for (int n = 0; n < 8; n++) {
                    int col = j * BC + n * 8 + t;   // c0/c2 column; c1/c3 is col+4
                    if (col     > row0) sacc[s][n][0] = -1e30f;
                    if (col + 4 > row0) sacc[s][n][1] = -1e30f;
                    if (col     > row1) sacc[s][n][2] = -1e30f;
                    if (col + 4 > row1) sacc[s][n][3] = -1e30f;
                }
            }
        }

        // ---- online softmax (per strip) ----
#pragma unroll
        for (int s = 0; s < 2; s++) {
            float tm0 = -INFINITY, tm1 = -INFINITY;
#pragma unroll
            for (int n = 0; n < 8; n++) {
                tm0 = fmaxf(tm0, fmaxf(sacc[s][n][0], sacc[s][n][1]));
                tm1 = fmaxf(tm1, fmaxf(sacc[s][n][2], sacc[s][n][3]));
            }
            tm0 = fmaxf(tm0, __shfl_xor_sync(0xFFFFFFFFu, tm0, 1));
            tm0 = fmaxf(tm0, __shfl_xor_sync(0xFFFFFFFFu, tm0, 2));
            tm1 = fmaxf(tm1, __shfl_xor_sync(0xFFFFFFFFu, tm1, 1));
            tm1 = fmaxf(tm1, __shfl_xor_sync(0xFFFFFFFFu, tm1, 2));

            float mn0 = fmaxf(mrow[s][0], tm0);
            float mn1 = fmaxf(mrow[s][1], tm1);
            float a0 = __expf(mrow[s][0] - mn0);
            float a1 = __expf(mrow[s][1] - mn1);

            float ls0 = 0.0f, ls1 = 0.0f;
#pragma unroll
            for (int n = 0; n < 8; n++) {
                sacc[s][n][0] = __expf(sacc[s][n][0] - mn0);
                sacc[s][n][1] = __expf(sacc[s][n][1] - mn0);
                sacc[s][n][2] = __expf(sacc[s][n][2] - mn1);
                sacc[s][n][3] = __expf(sacc[s][n][3] - mn1);
                ls0 += sacc[s][n][0] + sacc[s][n][1];
                ls1 += sacc[s][n][2] + sacc[s][n][3];
            }
            ls0 += __shfl_xor_sync(0xFFFFFFFFu, ls0, 1);
            ls0 += __shfl_xor_sync(0xFFFFFFFFu, ls0, 2);
            ls1 += __shfl_xor_sync(0xFFFFFFFFu, ls1, 1);
            ls1 += __shfl_xor_sync(0xFFFFFFFFu, ls1, 2);

            lrow[s][0] = lrow[s][0] * a0 + ls0;
            lrow[s][1] = lrow[s][1] * a1 + ls1;
            mrow[s][0] = mn0;
            mrow[s][1] = mn1;

#pragma unroll
            for (int n = 0; n < 8; n++) {
                oacc[s][n][0] *= a0; oacc[s][n][1] *= a0;
                oacc[s][n][2] *= a1; oacc[s][n][3] *= a1;
            }
        }

        // ---- O += P @ V : sacc IS the A-fragment; one B-load -> two mmas ----
        const uint32_t* sVb = sV + t * VSTR + g;
#pragma unroll
        for (int kt = 0; kt < 8; kt++) {
            uint32_t pa[2][4];
#pragma unroll
            for (int s = 0; s < 2; s++) {
                pa[s][0] = f2tf32(sacc[s][kt][0]);  // P[row g   ][kt*8 + t    ]
                pa[s][1] = f2tf32(sacc[s][kt][2]);  // P[row g+8 ][kt*8 + t    ]
                pa[s][2] = f2tf32(sacc[s][kt][1]);  // P[row g   ][kt*8 + t + 4]
                pa[s][3] = f2tf32(sacc[s][kt][3]);  // P[row g+8 ][kt*8 + t + 4]
            }
#pragma unroll
            for (int dn = 0; dn < 8; dn++) {
                uint32_t b0 = sVb[(kt * 8)     * VSTR + dn * 8];
                uint32_t b1 = sVb[(kt * 8 + 4) * VSTR + dn * 8];
                mma_tf32(oacc[0][dn], pa[0], b0, b1);
                mma_tf32(oacc[1][dn], pa[1], b0, b1);
            }
        }
    }

    // ---- epilogue: normalize and store (both strips) ----
    float* Ob = O + ((size_t)bh * SEQ + wbase) * HD;
#pragma unroll
    for (int s = 0; s < 2; s++) {
        const float inv0 = 1.0f / lrow[s][0];
        const float inv1 = 1.0f / lrow[s][1];
#pragma unroll
        for (int dn = 0; dn < 8; dn++) {
            float2 v0 = make_float2(oacc[s][dn][0] * inv0, oacc[s][dn][1] * inv0);
            float2 v1 = make_float2(oacc[s][dn][2] * inv1, oacc[s][dn][3] * inv1);
            *(float2*)(Ob + (s * 16 + g)     * HD + dn * 8 + 2 * t) = v0;
            *(float2*)(Ob + (s * 16 + g + 8) * HD + dn * 8 + 2 * t) = v1;
        }
    }
}

extern "C" void kernel_launch(void* const* d_in, const int* in_sizes, int n_in,
                              void* d_out, int out_size) {
    const float* V = (const float*)d_in[0];
    const float* Q = (const float*)d_in[1];
    const float* K = (const float*)d_in[2];
    float* O = (float*)d_out;

    dim3 grid(SEQ / BR, 32);  // (16 q-tiles, B*H heads)
    dim3 block(128);
    fa_tf32_kernel<<<grid, block>>>(Q, K, V, O);
}